// round 13
// baseline (speedup 1.0000x reference)
#include <cuda_runtime.h>
#include <cuda_pipeline.h>
#include <cstdint>

#define NPTS 262144
#define PPL 128
#define DD 64
#define PN ((size_t)PPL * (size_t)NPTS)

typedef unsigned long long u64;

// Scratch (no allocation allowed -> __device__ globals)
__device__ float g_h2[(size_t)NPTS * DD];          // 64 MB: fc2 features
__device__ unsigned char g_nib[(size_t)PPL * (NPTS / 4)];  // 8 MB: on|off<<4 per 4 pts

// ---------------------------------------------------------------------------
// Packed f32x2 helpers (FFMA2 — bit-exact pair of fp32 FMAs)
// ---------------------------------------------------------------------------
__device__ __forceinline__ u64 pack_dup(float x) {
    u64 r;
    asm("mov.b64 %0, {%1, %1};" : "=l"(r) : "f"(x));
    return r;
}
__device__ __forceinline__ u64 pack2(float lo, float hi) {
    u64 r;
    asm("mov.b64 %0, {%1, %2};" : "=l"(r) : "f"(lo), "f"(hi));
    return r;
}
__device__ __forceinline__ void unpack2(u64 v, float& lo, float& hi) {
    asm("mov.b64 {%0, %1}, %2;" : "=f"(lo), "=f"(hi) : "l"(v));
}
__device__ __forceinline__ void ffma2(u64& acc, u64 a, u64 b) {
    asm("fma.rn.f32x2 %0, %1, %2, %0;" : "+l"(acc) : "l"(a), "l"(b));
}

// ---------------------------------------------------------------------------
// Kernel 1: per-point MLP (R10 pipeline) + fused VECTORIZED mask phase.
// MLP: block = 128 pts x 64 ch, 128 threads, cp.async double-buffered L1.
// Mask phase: warp w owns planes [32w,32w+32), lane l owns points 4l..4l+3;
// one STG.128 per array per (plane, point-quad); nibble byte -> g_nib.
// ---------------------------------------------------------------------------
#define MLP_TPB 128
#define MLP_PTS 128
#define SH_W_FLOATS 4096
#define SH_A_QUADS 2048
#define MLP_SMEM_BYTES (SH_W_FLOATS * 4 + SH_A_QUADS * 16)

__global__ void __launch_bounds__(MLP_TPB) mlp_kernel(
    const float* __restrict__ feature, const float* __restrict__ feature_geo,
    const float* __restrict__ w1, const float* __restrict__ b1,
    const float* __restrict__ g1, const float* __restrict__ be1,
    const float* __restrict__ m1, const float* __restrict__ v1,
    const float* __restrict__ w2, const float* __restrict__ b2,
    const float* __restrict__ g2, const float* __restrict__ be2,
    const float* __restrict__ m2, const float* __restrict__ v2,
    const float* __restrict__ w3, const float* __restrict__ b3,
    const float* __restrict__ xyz, const float* __restrict__ centers,
    const float* __restrict__ plane_center, const float* __restrict__ plane_normal,
    const float* __restrict__ pmin, const float* __restrict__ pmax,
    float* __restrict__ out)
{
    extern __shared__ float smemf[];
    float* sh_w = smemf;                             // SH_W_FLOATS
    float4* sh_a = (float4*)(smemf + SH_W_FLOATS);   // SH_A_QUADS

    __shared__ float A1[64], C1[64], A2[64], C2[64], W3s[64];
    __shared__ float sh_s[128 * 8];
    __shared__ __align__(16) float shPX[128], shPY[128], shPZ[128], shS[128];
    __shared__ float B3;

    const int tid = threadIdx.x;
    const int pg  = tid & 15;
    const int cg  = tid >> 4;
    const int swz = pg & 7;
    const int base = blockIdx.x * MLP_PTS;

    // --- prologue: prefetch layer-1 chunks 0 and 1 (acts + weights) --------
    const float4* fsrc0 = (const float4*)(feature + (size_t)base * 64);
    const float4* fsrc1 = (const float4*)(feature_geo + (size_t)base * 64);
    const float4* w1v = (const float4*)w1;

    #pragma unroll
    for (int c = 0; c < 2; c++) {
        const float4* fs = fsrc0;
        float4* abuf = sh_a + (c & 1) * 1024;
        float4* wbuf = (float4*)(sh_w + (c & 1) * 2048);
        int c8 = (c & 1) * 8;
        #pragma unroll
        for (int i = 0; i < 8; i++) {
            int idx = tid + i * 128;
            int pt = idx >> 3, q = idx & 7;
            __pipeline_memcpy_async(&abuf[pt * 8 + (q ^ ((pt >> 3) & 7))],
                                    &fs[pt * 16 + c8 + q], 16);
        }
        #pragma unroll
        for (int i = 0; i < 4; i++) {
            int idx = tid + i * 128;
            __pipeline_memcpy_async(&wbuf[idx], &w1v[c * 512 + idx], 16);
        }
        __pipeline_commit();
    }

    if (tid < 64) {
        float s1 = g1[tid] * rsqrtf(v1[tid] + 1e-5f);
        A1[tid] = s1;
        C1[tid] = (b1[tid] - m1[tid]) * s1 + be1[tid];
        float s2 = g2[tid] * rsqrtf(v2[tid] + 1e-5f);
        A2[tid] = s2;
        C2[tid] = (b2[tid] - m2[tid]) * s2 + be2[tid];
        W3s[tid] = w3[tid];
        if (tid == 0) B3 = b3[0];
    }

    u64 acc[32];
    #pragma unroll
    for (int i = 0; i < 32; i++) acc[i] = 0ull;

    // ---- Layer 1: 4 chunks of 32 k, double-buffered ----
    #pragma unroll 1
    for (int c = 0; c < 4; c++) {
        if (c == 3) __pipeline_wait_prior(0);
        else        __pipeline_wait_prior(1);
        __syncthreads();

        const float* wbuf = sh_w + (c & 1) * 2048;
        const float4* abuf = sh_a + (c & 1) * 1024;

        #pragma unroll 1
        for (int kq = 0; kq < 8; kq++) {
            u64 wp[16];
            #pragma unroll
            for (int j = 0; j < 4; j++) {
                const float4* wr = (const float4*)(wbuf + (4 * kq + j) * 64 + 8 * cg);
                float4 wv0 = wr[0], wv1 = wr[1];
                wp[j * 4 + 0] = pack2(wv0.x, wv0.y);
                wp[j * 4 + 1] = pack2(wv0.z, wv0.w);
                wp[j * 4 + 2] = pack2(wv1.x, wv1.y);
                wp[j * 4 + 3] = pack2(wv1.z, wv1.w);
            }
            #pragma unroll
            for (int p = 0; p < 8; p++) {
                float4 a = abuf[(8 * pg + p) * 8 + (kq ^ swz)];
                u64 ad;
                ad = pack_dup(a.x);
                ffma2(acc[p * 4 + 0], ad, wp[0]);  ffma2(acc[p * 4 + 1], ad, wp[1]);
                ffma2(acc[p * 4 + 2], ad, wp[2]);  ffma2(acc[p * 4 + 3], ad, wp[3]);
                ad = pack_dup(a.y);
                ffma2(acc[p * 4 + 0], ad, wp[4]);  ffma2(acc[p * 4 + 1], ad, wp[5]);
                ffma2(acc[p * 4 + 2], ad, wp[6]);  ffma2(acc[p * 4 + 3], ad, wp[7]);
                ad = pack_dup(a.z);
                ffma2(acc[p * 4 + 0], ad, wp[8]);  ffma2(acc[p * 4 + 1], ad, wp[9]);
                ffma2(acc[p * 4 + 2], ad, wp[10]); ffma2(acc[p * 4 + 3], ad, wp[11]);
                ad = pack_dup(a.w);
                ffma2(acc[p * 4 + 0], ad, wp[12]); ffma2(acc[p * 4 + 1], ad, wp[13]);
                ffma2(acc[p * 4 + 2], ad, wp[14]); ffma2(acc[p * 4 + 3], ad, wp[15]);
            }
        }
        __syncthreads();

        if (c < 2) {
            int cn = c + 2;
            float4* abuf2 = sh_a + (cn & 1) * 1024;
            float4* wbuf2 = (float4*)(sh_w + (cn & 1) * 2048);
            int c8 = (cn & 1) * 8;
            #pragma unroll
            for (int i = 0; i < 8; i++) {
                int idx = tid + i * 128;
                int pt = idx >> 3, q = idx & 7;
                __pipeline_memcpy_async(&abuf2[pt * 8 + (q ^ ((pt >> 3) & 7))],
                                        &fsrc1[pt * 16 + c8 + q], 16);
            }
            #pragma unroll
            for (int i = 0; i < 4; i++) {
                int idx = tid + i * 128;
                __pipeline_memcpy_async(&wbuf2[idx], &w1v[cn * 512 + idx], 16);
            }
            __pipeline_commit();
        }
    }

    // BN1 + ReLU -> h1 into full sh_a
    #pragma unroll
    for (int p = 0; p < 8; p++) {
        float v[8];
        #pragma unroll
        for (int c = 0; c < 4; c++) unpack2(acc[p * 4 + c], v[2 * c], v[2 * c + 1]);
        float4 lo, hi;
        lo.x = fmaxf(fmaf(v[0], A1[8 * cg + 0], C1[8 * cg + 0]), 0.f);
        lo.y = fmaxf(fmaf(v[1], A1[8 * cg + 1], C1[8 * cg + 1]), 0.f);
        lo.z = fmaxf(fmaf(v[2], A1[8 * cg + 2], C1[8 * cg + 2]), 0.f);
        lo.w = fmaxf(fmaf(v[3], A1[8 * cg + 3], C1[8 * cg + 3]), 0.f);
        hi.x = fmaxf(fmaf(v[4], A1[8 * cg + 4], C1[8 * cg + 4]), 0.f);
        hi.y = fmaxf(fmaf(v[5], A1[8 * cg + 5], C1[8 * cg + 5]), 0.f);
        hi.z = fmaxf(fmaf(v[6], A1[8 * cg + 6], C1[8 * cg + 6]), 0.f);
        hi.w = fmaxf(fmaf(v[7], A1[8 * cg + 7], C1[8 * cg + 7]), 0.f);
        int qb = (8 * pg + p) * 16;
        sh_a[qb + ((2 * cg + 0) ^ swz)] = lo;
        sh_a[qb + ((2 * cg + 1) ^ swz)] = hi;
        acc[p * 4 + 0] = 0ull; acc[p * 4 + 1] = 0ull;
        acc[p * 4 + 2] = 0ull; acc[p * 4 + 3] = 0ull;
    }
    {   // prefetch w2
        const float4* w2v = (const float4*)w2;
        float4* wdst = (float4*)sh_w;
        #pragma unroll
        for (int i = 0; i < 8; i++) {
            int idx = tid + i * 128;
            __pipeline_memcpy_async(&wdst[idx], &w2v[idx], 16);
        }
        __pipeline_commit();
    }
    __pipeline_wait_prior(0);
    __syncthreads();

    // ---- Layer 2: K=64
    #pragma unroll 1
    for (int kq = 0; kq < 16; kq++) {
        u64 wp[16];
        #pragma unroll
        for (int j = 0; j < 4; j++) {
            const float4* wr = (const float4*)(sh_w + (4 * kq + j) * 64 + 8 * cg);
            float4 wv0 = wr[0], wv1 = wr[1];
            wp[j * 4 + 0] = pack2(wv0.x, wv0.y);
            wp[j * 4 + 1] = pack2(wv0.z, wv0.w);
            wp[j * 4 + 2] = pack2(wv1.x, wv1.y);
            wp[j * 4 + 3] = pack2(wv1.z, wv1.w);
        }
        #pragma unroll
        for (int p = 0; p < 8; p++) {
            float4 a = sh_a[(8 * pg + p) * 16 + (kq ^ swz)];
            u64 ad;
            ad = pack_dup(a.x);
            ffma2(acc[p * 4 + 0], ad, wp[0]);  ffma2(acc[p * 4 + 1], ad, wp[1]);
            ffma2(acc[p * 4 + 2], ad, wp[2]);  ffma2(acc[p * 4 + 3], ad, wp[3]);
            ad = pack_dup(a.y);
            ffma2(acc[p * 4 + 0], ad, wp[4]);  ffma2(acc[p * 4 + 1], ad, wp[5]);
            ffma2(acc[p * 4 + 2], ad, wp[6]);  ffma2(acc[p * 4 + 3], ad, wp[7]);
            ad = pack_dup(a.z);
            ffma2(acc[p * 4 + 0], ad, wp[8]);  ffma2(acc[p * 4 + 1], ad, wp[9]);
            ffma2(acc[p * 4 + 2], ad, wp[10]); ffma2(acc[p * 4 + 3], ad, wp[11]);
            ad = pack_dup(a.w);
            ffma2(acc[p * 4 + 0], ad, wp[12]); ffma2(acc[p * 4 + 1], ad, wp[13]);
            ffma2(acc[p * 4 + 2], ad, wp[14]); ffma2(acc[p * 4 + 3], ad, wp[15]);
        }
    }

    // BN2 + ReLU -> h2 (direct STG.128), fc3 partials into sh_s
    #pragma unroll
    for (int p = 0; p < 8; p++) {
        float v[8];
        #pragma unroll
        for (int c = 0; c < 4; c++) unpack2(acc[p * 4 + c], v[2 * c], v[2 * c + 1]);
        float s = 0.f;
        #pragma unroll
        for (int j = 0; j < 8; j++) {
            int c = 8 * cg + j;
            v[j] = fmaxf(fmaf(v[j], A2[c], C2[c]), 0.f);
            s = fmaf(v[j], W3s[c], s);
        }
        float* hrow = g_h2 + (size_t)(base + 8 * pg + p) * 64 + 8 * cg;
        ((float4*)hrow)[0] = make_float4(v[0], v[1], v[2], v[3]);
        ((float4*)hrow)[1] = make_float4(v[4], v[5], v[6], v[7]);
        sh_s[(8 * pg + p) * 8 + cg] = s;
    }
    __syncthreads();   // sh_s complete; sh_w/sh_a dead -> reusable for planes

    // ---- stage plane params (stride 12) into dead dynamic smem + point data
    float* PP = smemf;
    if (tid < 128) {
        int p = tid;
        float nx = plane_normal[p * 3 + 0];
        float ny = plane_normal[p * 3 + 1];
        float nz = plane_normal[p * 3 + 2];
        PP[p * 12 + 0] = nx;
        PP[p * 12 + 1] = ny;
        PP[p * 12 + 2] = nz;
        PP[p * 12 + 3] = plane_center[p * 3 + 0] * nx
                       + plane_center[p * 3 + 1] * ny
                       + plane_center[p * 3 + 2] * nz;
        PP[p * 12 + 4] = pmin[p * 3 + 0];
        PP[p * 12 + 5] = pmin[p * 3 + 1];
        PP[p * 12 + 6] = pmin[p * 3 + 2];
        PP[p * 12 + 7] = pmax[p * 3 + 0];
        PP[p * 12 + 8] = pmax[p * 3 + 1];
        PP[p * 12 + 9] = pmax[p * 3 + 2];
    }
    {   // point data: thread tid owns point base+tid
        const int n = base + tid;
        shPX[tid] = xyz[n * 3 + 0] + centers[0];
        shPY[tid] = xyz[n * 3 + 1] + centers[1];
        shPZ[tid] = xyz[n * 3 + 2] + centers[2];
        const float* sp = sh_s + tid * 8;
        float s = B3;
        #pragma unroll
        for (int j = 0; j < 8; j++) s += sp[j];
        shS[tid] = fmaxf(s, 0.f);
    }
    __syncthreads();

    // ---- vectorized mask phase: warp w -> planes [32w,32w+32), lane l -> pts 4l..4l+3
    {
        const int l = tid & 31;
        const int w = tid >> 5;
        float4 X = *(const float4*)(shPX + 4 * l);
        float4 Y = *(const float4*)(shPY + 4 * l);
        float4 Z = *(const float4*)(shPZ + 4 * l);
        float4 S = *(const float4*)(shS + 4 * l);
        const float Xa[4] = {X.x, X.y, X.z, X.w};
        const float Ya[4] = {Y.x, Y.y, Y.z, Y.w};
        const float Za[4] = {Z.x, Z.y, Z.z, Z.w};
        const float Sa[4] = {S.x, S.y, S.z, S.w};
        float* oS  = out;
        float* oM  = out + PN;
        float* oOn = out + 2 * PN;
        float* oOf = out + 3 * PN;

        #pragma unroll 2
        for (int pi = 0; pi < 32; pi++) {
            const int p = 32 * w + pi;
            const float4* pv = (const float4*)(PP + p * 12);
            float4 P0 = pv[0];   // nx ny nz off
            float4 P1 = pv[1];   // mn0 mn1 mn2 mx0
            float4 P2 = pv[2];   // mx1 mx2 - -
            float4 vS, vM, vOn, vOf;
            float* pS = &vS.x; float* pM = &vM.x;
            float* pO = &vOn.x; float* pF = &vOf.x;
            unsigned nib = 0;
            #pragma unroll
            for (int j = 0; j < 4; j++) {
                float px = Xa[j], py = Ya[j], pz = Za[j], s = Sa[j];
                bool rok = (P1.w == 0.f || (px >= P1.x && px < P1.w))
                        && (P2.x == 0.f || (py >= P1.y && py < P2.x))
                        && (P2.y == 0.f || (pz >= P1.z && pz < P2.y));
                float dist = fabsf(px * P0.x + py * P0.y + pz * P0.z - P0.w);
                bool mask = rok && (dist < 0.1f);
                bool onm  = mask && (s > 0.f);
                bool offm = mask && (s <= 0.f);
                pS[j] = mask ? s : 0.f;
                pM[j] = mask ? 1.f : 0.f;
                pO[j] = onm ? 1.f : 0.f;
                pF[j] = offm ? 1.f : 0.f;
                nib |= (onm ? (1u << j) : 0u) | (offm ? (16u << j) : 0u);
            }
            const size_t o = (size_t)p * NPTS + base + 4 * l;
            __stcs((float4*)(oS + o),  vS);
            __stcs((float4*)(oM + o),  vM);
            __stcs((float4*)(oOn + o), vOn);
            __stcs((float4*)(oOf + o), vOf);
            g_nib[(size_t)p * (NPTS / 4) + ((base >> 2) + l)] = (unsigned char)nib;
        }
    }
}

// ---------------------------------------------------------------------------
// Kernel 2: zero the pooled-feature region (atomicMax accumulates into it)
// ---------------------------------------------------------------------------
__global__ void zero_feats(float* __restrict__ out) {
    size_t i = (size_t)blockIdx.x * 256 + threadIdx.x;  // 16384 elements
    out[4 * PN + i] = 0.f;
}

// ---------------------------------------------------------------------------
// Kernel 3: pool-only. Expand nibbles -> lists, gather h2, atomicMax.
// grid = (N/2048, P), 256 threads.
// ---------------------------------------------------------------------------
#define P2_TPB 256
#define P2_PTS 2048

__global__ void __launch_bounds__(P2_TPB) pool_kernel(float* __restrict__ out)
{
    const int p = blockIdx.y;
    const int cbase = blockIdx.x * P2_PTS;
    const int tid = threadIdx.x;

    __shared__ unsigned shOn[64], shOff[64];
    __shared__ int lstOn[P2_PTS];
    __shared__ int lstOff[P2_PTS];
    __shared__ int cntOn, cntOff;
    if (tid == 0) { cntOn = 0; cntOff = 0; }
    if (tid < 64) { shOn[tid] = 0u; shOff[tid] = 0u; }
    __syncthreads();

    // expand nibble bytes (512 per chunk, as 128 words) into point lists
    if (tid < 128) {
        unsigned wv = ((const unsigned*)g_nib)[(size_t)p * (NPTS / 16) + (cbase >> 4) + tid];
        int bn = cbase + tid * 16;
        unsigned on16 = 0, off16 = 0;
        #pragma unroll
        for (int b = 0; b < 4; b++) {
            unsigned byte = (wv >> (8 * b)) & 0xffu;
            on16  |= (byte & 0xfu) << (4 * b);
            off16 |= (byte >> 4) << (4 * b);
        }
        while (on16) {
            int b = __ffs(on16) - 1;
            on16 &= on16 - 1;
            lstOn[atomicAdd(&cntOn, 1)] = bn + b;
        }
        while (off16) {
            int b = __ffs(off16) - 1;
            off16 &= off16 - 1;
            lstOff[atomicAdd(&cntOff, 1)] = bn + b;
        }
    }
    __syncthreads();

    // Cooperative masked max-pool of h2 rows: 4 rows in flight x 64 dims.
    const int d = tid & 63;
    const int g = tid >> 6;
    unsigned mOn = 0u, mOf = 0u;
    const int con = cntOn, cof = cntOff;
    for (int idx = g; idx < con; idx += 4) {
        int nn = lstOn[idx];
        mOn = max(mOn, __float_as_uint(g_h2[(size_t)nn * 64 + d]));
    }
    for (int idx = g; idx < cof; idx += 4) {
        int nn = lstOff[idx];
        mOf = max(mOf, __float_as_uint(g_h2[(size_t)nn * 64 + d]));
    }
    if (mOn) atomicMax(&shOn[d], mOn);
    if (mOf) atomicMax(&shOff[d], mOf);
    __syncthreads();

    // h2 >= 0 so uint-bit atomicMax against 0-initialized output is exact.
    if (tid < 64) {
        unsigned v = shOn[tid];
        if (v) atomicMax((unsigned*)(out + 4 * PN + (size_t)p * 64 + tid), v);
    } else if (tid < 128) {
        unsigned v = shOff[tid - 64];
        if (v) atomicMax((unsigned*)(out + 4 * PN + (size_t)PPL * 64 + (size_t)p * 64 + (tid - 64)), v);
    }
}

// ---------------------------------------------------------------------------
extern "C" void kernel_launch(void* const* d_in, const int* in_sizes, int n_in,
                              void* d_out, int out_size) {
    const float* feature      = (const float*)d_in[0];
    const float* feature_geo  = (const float*)d_in[1];
    const float* xyz          = (const float*)d_in[2];
    const float* centers      = (const float*)d_in[3];
    const float* plane_center = (const float*)d_in[4];
    const float* plane_normal = (const float*)d_in[5];
    const float* pxyz_min     = (const float*)d_in[6];
    const float* pxyz_max     = (const float*)d_in[7];
    const float* w1 = (const float*)d_in[8];
    const float* b1 = (const float*)d_in[9];
    const float* g1 = (const float*)d_in[10];
    const float* be1 = (const float*)d_in[11];
    const float* m1 = (const float*)d_in[12];
    const float* v1 = (const float*)d_in[13];
    const float* w2 = (const float*)d_in[14];
    const float* b2 = (const float*)d_in[15];
    const float* g2 = (const float*)d_in[16];
    const float* be2 = (const float*)d_in[17];
    const float* m2 = (const float*)d_in[18];
    const float* v2 = (const float*)d_in[19];
    const float* w3 = (const float*)d_in[20];
    const float* b3 = (const float*)d_in[21];
    float* out = (float*)d_out;

    cudaFuncSetAttribute((const void*)mlp_kernel,
                         cudaFuncAttributeMaxDynamicSharedMemorySize,
                         MLP_SMEM_BYTES);

    zero_feats<<<64, 256>>>(out);
    mlp_kernel<<<NPTS / MLP_PTS, MLP_TPB, MLP_SMEM_BYTES>>>(
        feature, feature_geo,
        w1, b1, g1, be1, m1, v1,
        w2, b2, g2, be2, m2, v2,
        w3, b3,
        xyz, centers, plane_center, plane_normal,
        pxyz_min, pxyz_max, out);
    dim3 grid2(NPTS / P2_PTS, PPL);
    pool_kernel<<<grid2, P2_TPB>>>(out);
}